// round 8
// baseline (speedup 1.0000x reference)
#include <cuda_runtime.h>
#include <cuda_bf16.h>
#include <math.h>
#include <stdint.h>

#define BATCH 2
#define S_LEN 2048
#define D_MODEL 1024
#define NHEAD 16
#define DHEAD 64
#define NEGBIG -1e30f

// fp32 scratch
__device__ float g_q[BATCH*NHEAD*S_LEN*DHEAD];
__device__ float g_k[BATCH*NHEAD*S_LEN*DHEAD];
__device__ float g_v[BATCH*NHEAD*S_LEN*DHEAD];
__device__ float g_att[BATCH*S_LEN*D_MODEL];

// bf16 hi/lo planes
__device__ __nv_bfloat16 g_xh[4096*1024],  g_xl[4096*1024];
__device__ __nv_bfloat16 g_ath[4096*1024], g_atl[4096*1024];
__device__ __nv_bfloat16 g_wqh[3072*1024], g_wql[3072*1024];   // transposed N x K
__device__ __nv_bfloat16 g_woh[1024*1024], g_wol[1024*1024];   // transposed N x K

__device__ __forceinline__ void bf16split(float x, __nv_bfloat16& hi, __nv_bfloat16& lo) {
    hi = __float2bfloat16_rn(x);
    lo = __float2bfloat16_rn(x - __bfloat162float(hi));
}

// ---------------------------------------------------------------------------
// Pre-pass 1: elementwise split (row-major preserved)
// ---------------------------------------------------------------------------
__global__ void split_plain_kernel(const float* __restrict__ in,
                                   __nv_bfloat16* __restrict__ hi,
                                   __nv_bfloat16* __restrict__ lo)
{
    int i = (blockIdx.x * 256 + threadIdx.x) * 4;
    float4 v = *reinterpret_cast<const float4*>(in + i);
    __nv_bfloat16 h0,l0,h1,l1,h2,l2,h3,l3;
    bf16split(v.x,h0,l0); bf16split(v.y,h1,l1);
    bf16split(v.z,h2,l2); bf16split(v.w,h3,l3);
    *reinterpret_cast<__nv_bfloat162*>(hi + i)     = __nv_bfloat162(h0,h1);
    *reinterpret_cast<__nv_bfloat162*>(hi + i + 2) = __nv_bfloat162(h2,h3);
    *reinterpret_cast<__nv_bfloat162*>(lo + i)     = __nv_bfloat162(l0,l1);
    *reinterpret_cast<__nv_bfloat162*>(lo + i + 2) = __nv_bfloat162(l2,l3);
}

// ---------------------------------------------------------------------------
// Pre-pass 2: split + transpose. in: R x C (fp32) -> hiT/loT: C x R (bf16)
// ---------------------------------------------------------------------------
__global__ void transpose_split_kernel(const float* __restrict__ in,
                                       __nv_bfloat16* __restrict__ hiT,
                                       __nv_bfloat16* __restrict__ loT,
                                       int R, int C)
{
    __shared__ float t[32][33];
    const int tx = threadIdx.x, ty = threadIdx.y;
    const int r0 = blockIdx.y * 32, c0 = blockIdx.x * 32;
    #pragma unroll
    for (int i = 0; i < 4; i++)
        t[ty + i*8][tx] = in[(long)(r0 + ty + i*8) * C + c0 + tx];
    __syncthreads();
    #pragma unroll
    for (int i = 0; i < 4; i++) {
        float v = t[tx][ty + i*8];
        __nv_bfloat16 h, l;
        bf16split(v, h, l);
        long o = (long)(c0 + ty + i*8) * R + r0 + tx;
        hiT[o] = h; loT[o] = l;
    }
}

// ---------------------------------------------------------------------------
// bf16 3-term GEMM, ldmatrix fragments, CTA tile 128x256, warp tile 64x64.
// C = A(MxK) @ B^T(NxK), K=1024. BK=32 double-buffered. 256 thr, 8 warps 2x4.
// smem: A planes 2x(128x40), B planes 2x(256x40), x2 buf = 120KB.
// ---------------------------------------------------------------------------
#define KP 40
#define APLANE (128*KP)
#define BPLANE (256*KP)
#define ABUF (2*APLANE)                 // Ah+Al per buffer (elements)
#define BBUF (2*BPLANE)
#define GEMM_SMEM_BYTES ((2*ABUF + 2*BBUF) * (int)sizeof(__nv_bfloat16))

__device__ __forceinline__ void cpasync16(__nv_bfloat16* smem, const __nv_bfloat16* g) {
    uint32_t s = (uint32_t)__cvta_generic_to_shared(smem);
    asm volatile("cp.async.cg.shared.global [%0], [%1], 16;\n" :: "r"(s), "l"(g));
}

__device__ __forceinline__ void mma_bf16(float* c, const uint32_t* a, const uint32_t* b) {
    asm volatile(
        "mma.sync.aligned.m16n8k16.row.col.f32.bf16.bf16.f32 "
        "{%0,%1,%2,%3}, {%4,%5,%6,%7}, {%8,%9}, {%0,%1,%2,%3};"
        : "+f"(c[0]), "+f"(c[1]), "+f"(c[2]), "+f"(c[3])
        : "r"(a[0]), "r"(a[1]), "r"(a[2]), "r"(a[3]), "r"(b[0]), "r"(b[1]));
}

__device__ __forceinline__ void ldsm_x4(uint32_t* r, uint32_t addr) {
    asm volatile("ldmatrix.sync.aligned.m8n8.x4.shared.b16 {%0,%1,%2,%3}, [%4];"
                 : "=r"(r[0]), "=r"(r[1]), "=r"(r[2]), "=r"(r[3]) : "r"(addr));
}

template<int N, bool IS_QKV>
__global__ __launch_bounds__(256, 1)
void bf16_gemm_kernel(const __nv_bfloat16* __restrict__ Ahg,
                      const __nv_bfloat16* __restrict__ Alg,
                      const __nv_bfloat16* __restrict__ Bhg,
                      const __nv_bfloat16* __restrict__ Blg,
                      float* __restrict__ Out)
{
    extern __shared__ __nv_bfloat16 smg[];
    // layout: [buf0: Ah Al Bh Bl][buf1: Ah Al Bh Bl]
    __nv_bfloat16* base = smg;

    const int K = 1024;
    const int tid  = threadIdx.x;
    const int lane = tid & 31;
    const int wid  = tid >> 5;
    const int wm   = wid & 1;        // 2 m-slabs of 64
    const int wn   = wid >> 1;       // 4 n-slabs of 64
    const int m0 = blockIdx.y * 128;
    const int n0 = blockIdx.x * 256;

    const int BUFE = ABUF + BBUF;    // elements per buffer

    // ldmatrix per-lane offset
    const int lrow = ((lane >> 3) & 1) * 8 + (lane & 7);
    const int lkq  = (lane >> 4) * 8;
    const uint32_t lmo = (uint32_t)((lrow * KP + lkq) * 2);

    const uint32_t sbase = (uint32_t)__cvta_generic_to_shared(base);

    float acc[4][8][4];
    #pragma unroll
    for (int mt = 0; mt < 4; mt++)
        #pragma unroll
        for (int nt = 0; nt < 8; nt++)
            #pragma unroll
            for (int i = 0; i < 4; i++) acc[mt][nt][i] = 0.f;

    auto load_tiles = [&](int k0, int buf) {
        __nv_bfloat16* Ah = base + buf*BUFE;
        __nv_bfloat16* Al = Ah + APLANE;
        __nv_bfloat16* Bh = Ah + ABUF;
        __nv_bfloat16* Bl = Bh + BPLANE;
        // A: 512 chunks per plane, 2/thread
        #pragma unroll
        for (int u = 0; u < 2; u++) {
            int c = tid + u*256;
            int row = c >> 2, kc = (c & 3) * 8;
            long go = (long)(m0 + row)*K + k0 + kc;
            cpasync16(&Ah[row*KP + kc], Ahg + go);
            cpasync16(&Al[row*KP + kc], Alg + go);
        }
        // B: 1024 chunks per plane, 4/thread
        #pragma unroll
        for (int u = 0; u < 4; u++) {
            int c = tid + u*256;
            int row = c >> 2, kc = (c & 3) * 8;
            long go = (long)(n0 + row)*K + k0 + kc;
            cpasync16(&Bh[row*KP + kc], Bhg + go);
            cpasync16(&Bl[row*KP + kc], Blg + go);
        }
        asm volatile("cp.async.commit_group;\n");
    };

    load_tiles(0, 0);

    const int NIT = K / 32;
    for (int it = 0; it < NIT; ++it) {
        const int buf = it & 1;
        asm volatile("cp.async.wait_group 0;\n");
        __syncthreads();
        if (it + 1 < NIT) load_tiles((it+1)*32, buf ^ 1);

        const uint32_t sAh = sbase + (uint32_t)(buf*BUFE*2);
        const uint32_t sAl = sAh + (uint32_t)(APLANE*2);
        const uint32_t sBh = sAh + (uint32_t)(ABUF*2);
        const uint32_t sBl = sBh + (uint32_t)(BPLANE*2);

        #pragma unroll
        for (int ks = 0; ks < 2; ks++) {
            const uint32_t kbo = (uint32_t)(ks*16*2) + lmo;

            uint32_t ahf[4][4], alf[4][4];
            #pragma unroll
            for (int mt = 0; mt < 4; mt++) {
                uint32_t ro = (uint32_t)((wm*64 + mt*16) * KP * 2);
                ldsm_x4(ahf[mt], sAh + ro + kbo);
                ldsm_x4(alf[mt], sAl + ro + kbo);
            }
            uint32_t bhf[8][2], blf[8][2];
            #pragma unroll
            for (int p = 0; p < 4; p++) {
                uint32_t ro = (uint32_t)((wn*64 + p*16) * KP * 2);
                uint32_t r[4];
                ldsm_x4(r, sBh + ro + kbo);
                bhf[2*p+0][0] = r[0]; bhf[2*p+1][0] = r[1];
                bhf[2*p+0][1] = r[2]; bhf[2*p+1][1] = r[3];
                ldsm_x4(r, sBl + ro + kbo);
                blf[2*p+0][0] = r[0]; blf[2*p+1][0] = r[1];
                blf[2*p+0][1] = r[2]; blf[2*p+1][1] = r[3];
            }
            #pragma unroll
            for (int mt = 0; mt < 4; mt++)
                #pragma unroll
                for (int nt = 0; nt < 8; nt++) {
                    mma_bf16(acc[mt][nt], ahf[mt], blf[nt]);  // hi*lo
                    mma_bf16(acc[mt][nt], alf[mt], bhf[nt]);  // lo*hi
                    mma_bf16(acc[mt][nt], ahf[mt], bhf[nt]);  // hi*hi
                }
        }
        __syncthreads();
    }

    #pragma unroll
    for (int mt = 0; mt < 4; mt++) {
        #pragma unroll
        for (int i = 0; i < 2; i++) {
            int row = m0 + wm*64 + mt*16 + (lane >> 2) + i*8;
            #pragma unroll
            for (int nt = 0; nt < 8; nt++) {
                int col = n0 + wn*64 + nt*8 + (lane & 3)*2;
                float2 v = make_float2(acc[mt][nt][i*2+0], acc[mt][nt][i*2+1]);
                if (IS_QKV) {
                    int b = row >> 11, s = row & 2047;
                    int which = col >> 10;
                    int h = (col >> 6) & 15;
                    int dh = col & 63;
                    float* dst = (which == 0) ? g_q : (which == 1) ? g_k : g_v;
                    *reinterpret_cast<float2*>(
                        &dst[(((long)(b*NHEAD + h))*S_LEN + s)*DHEAD + dh]) = v;
                } else {
                    *reinterpret_cast<float2*>(&Out[(long)row*N + col]) = v;
                }
            }
        }
    }
}

// ---------------------------------------------------------------------------
// Banded attention (R4 layout): Qs/Ks pitch 65, S overlays K. 2 CTAs/SM.
// ---------------------------------------------------------------------------
#define QS_P 65
#define KS_P 65
#define ATTN_SMEM_FLOATS (64*QS_P + 192*KS_P + 192*64)

__global__ __launch_bounds__(256)
void attn_kernel(const float* __restrict__ bias)
{
    extern __shared__ float sm[];
    float* Qs = sm;
    float* Ks = sm + 64*QS_P;
    float* Vs = sm + 64*QS_P + 192*KS_P;
    float* Ss = Ks;

    const int tid = threadIdx.x;
    const int qt = blockIdx.x;
    const int bh = blockIdx.y;
    const int qstart = qt * 64;
    const int jbase = qstart - 128;

    const float* qg = g_q + (long)bh * S_LEN * DHEAD;
    const float* kg = g_k + (long)bh * S_LEN * DHEAD;
    const float* vg = g_v + (long)bh * S_LEN * DHEAD;

    for (int idx = tid; idx < 64*64; idx += 256)
        Qs[(idx >> 6)*QS_P + (idx & 63)] = qg[(long)(qstart + (idx >> 6))*DHEAD + (idx & 63)];
    for (int idx = tid; idx < 192*64; idx += 256) {
        int j = jbase + (idx >> 6);
        float kv = 0.f, vv = 0.f;
        if (j >= 0) {
            kv = kg[(long)j*DHEAD + (idx & 63)];
            vv = vg[(long)j*DHEAD + (idx & 63)];
        }
        Ks[(idx >> 6)*KS_P + (idx & 63)] = kv;
        Vs[idx] = vv;
    }
    __syncthreads();

    const int ty = tid >> 4, tx = tid & 15;

    {
        float acc[4][12];
        #pragma unroll
        for (int i = 0; i < 4; i++)
            #pragma unroll
            for (int j = 0; j < 12; j++) acc[i][j] = 0.f;

        #pragma unroll 4
        for (int k = 0; k < 64; k++) {
            float rq[4], rk[12];
            #pragma unroll
            for (int i = 0; i < 4; i++) rq[i] = Qs[(ty*4+i)*QS_P + k];
            #pragma unroll
            for (int j = 0; j < 12; j++) rk[j] = Ks[(tx*12+j)*KS_P + k];
            #pragma unroll
            for (int i = 0; i < 4; i++)
                #pragma unroll
                for (int j = 0; j < 12; j++)
                    acc[i][j] = fmaf(rq[i], rk[j], acc[i][j]);
        }
        __syncthreads();

        const float scale = 0.125f;
        const float* bb = bias + (long)bh * S_LEN * S_LEN;
        #pragma unroll
        for (int i = 0; i < 4; i++) {
            int gi = qstart + ty*4 + i;
            #pragma unroll
            for (int j = 0; j < 12; j++) {
                int c = tx*12 + j;
                int gj = jbase + c;
                float val = NEGBIG;
                if (gj >= 0 && gj <= gi && (gi - gj) <= 128)
                    val = acc[i][j]*scale + bb[(long)gi*S_LEN + gj];
                Ss[(ty*4+i)*192 + c] = val;
            }
        }
    }
    __syncthreads();

    {
        const int w = tid >> 5, lane = tid & 31;
        for (int rr = 0; rr < 8; rr++) {
            int r = w*8 + rr;
            float vals[6];
            float m = NEGBIG;
            #pragma unroll
            for (int t = 0; t < 6; t++) {
                vals[t] = Ss[r*192 + t*32 + lane];
                m = fmaxf(m, vals[t]);
            }
            #pragma unroll
            for (int o = 16; o > 0; o >>= 1)
                m = fmaxf(m, __shfl_xor_sync(0xffffffffu, m, o));
            float ssum = 0.f;
            #pragma unroll
            for (int t = 0; t < 6; t++) {
                vals[t] = __expf(vals[t] - m);
                ssum += vals[t];
            }
            #pragma unroll
            for (int o = 16; o > 0; o >>= 1)
                ssum += __shfl_xor_sync(0xffffffffu, ssum, o);
            float inv = 1.f / ssum;
            #pragma unroll
            for (int t = 0; t < 6; t++)
                Ss[r*192 + t*32 + lane] = vals[t] * inv;
        }
    }
    __syncthreads();

    {
        float acc[4][4];
        #pragma unroll
        for (int i = 0; i < 4; i++)
            #pragma unroll
            for (int j = 0; j < 4; j++) acc[i][j] = 0.f;

        #pragma unroll 4
        for (int k = 0; k < 192; k++) {
            float rp[4], rv[4];
            #pragma unroll
            for (int i = 0; i < 4; i++) rp[i] = Ss[(ty*4+i)*192 + k];
            #pragma unroll
            for (int j = 0; j < 4; j++) rv[j] = Vs[k*64 + tx*4 + j];
            #pragma unroll
            for (int i = 0; i < 4; i++)
                #pragma unroll
                for (int j = 0; j < 4; j++)
                    acc[i][j] = fmaf(rp[i], rv[j], acc[i][j]);
        }

        const int b = bh >> 4, h = bh & 15;
        #pragma unroll
        for (int i = 0; i < 4; i++) {
            int gi = qstart + ty*4 + i;
            #pragma unroll
            for (int j = 0; j < 4; j++) {
                g_att[((long)(b*S_LEN + gi))*D_MODEL + h*DHEAD + tx*4 + j] = acc[i][j];
            }
        }
    }
}

// ---------------------------------------------------------------------------
extern "C" void kernel_launch(void* const* d_in, const int* in_sizes, int n_in,
                              void* d_out, int out_size)
{
    const float* x    = (const float*)d_in[0];
    const float* bias = (const float*)d_in[1];
    // d_in[2] = causal mask (recomputed analytically in-kernel)
    const float* Wqkv = (const float*)d_in[3];
    const float* Wout = (const float*)d_in[4];
    float* out = (float*)d_out;

    __nv_bfloat16 *xh, *xl, *ath, *atl, *wqh, *wql, *woh, *wol;
    cudaGetSymbolAddress((void**)&xh,  g_xh);  cudaGetSymbolAddress((void**)&xl,  g_xl);
    cudaGetSymbolAddress((void**)&ath, g_ath); cudaGetSymbolAddress((void**)&atl, g_atl);
    cudaGetSymbolAddress((void**)&wqh, g_wqh); cudaGetSymbolAddress((void**)&wql, g_wql);
    cudaGetSymbolAddress((void**)&woh, g_woh); cudaGetSymbolAddress((void**)&wol, g_wol);
    float* att; cudaGetSymbolAddress((void**)&att, g_att);

    cudaFuncSetAttribute(bf16_gemm_kernel<3072, true>,
                         cudaFuncAttributeMaxDynamicSharedMemorySize, GEMM_SMEM_BYTES);
    cudaFuncSetAttribute(bf16_gemm_kernel<1024, false>,
                         cudaFuncAttributeMaxDynamicSharedMemorySize, GEMM_SMEM_BYTES);
    cudaFuncSetAttribute(attn_kernel,
                         cudaFuncAttributeMaxDynamicSharedMemorySize,
                         ATTN_SMEM_FLOATS * (int)sizeof(float));

    // Pre-passes: split x; split+transpose weights
    split_plain_kernel<<<4096, 256>>>(x, xh, xl);
    transpose_split_kernel<<<dim3(3072/32, 1024/32), dim3(32, 8)>>>(Wqkv, wqh, wql, 1024, 3072);
    transpose_split_kernel<<<dim3(1024/32, 1024/32), dim3(32, 8)>>>(Wout, woh, wol, 1024, 1024);

    // QKV projection (M=4096, N=3072), CTA tile 128x256
    bf16_gemm_kernel<3072, true><<<dim3(12, 32), 256, GEMM_SMEM_BYTES>>>(
        xh, xl, wqh, wql, nullptr);

    // Banded attention
    attn_kernel<<<dim3(32, 32), 256, ATTN_SMEM_FLOATS * (int)sizeof(float)>>>(bias);

    // Split attention output, then output projection (M=4096, N=1024)
    split_plain_kernel<<<4096, 256>>>(att, ath, atl);
    bf16_gemm_kernel<1024, false><<<dim3(4, 32), 256, GEMM_SMEM_BYTES>>>(
        ath, atl, woh, wol, out);
}

// round 9
// speedup vs baseline: 1.0393x; 1.0393x over previous
#include <cuda_runtime.h>
#include <cuda_bf16.h>
#include <math.h>
#include <stdint.h>

#define BATCH 2
#define S_LEN 2048
#define D_MODEL 1024
#define NHEAD 16
#define DHEAD 64
#define NEGBIG -1e30f

// fp32 scratch
__device__ float g_q[BATCH*NHEAD*S_LEN*DHEAD];
__device__ float g_k[BATCH*NHEAD*S_LEN*DHEAD];
__device__ float g_v[BATCH*NHEAD*S_LEN*DHEAD];

// bf16 hi/lo planes
__device__ __nv_bfloat16 g_xh[4096*1024],  g_xl[4096*1024];
__device__ __nv_bfloat16 g_ath[4096*1024], g_atl[4096*1024];   // attention out planes
__device__ __nv_bfloat16 g_wqh[3072*1024], g_wql[3072*1024];   // transposed N x K
__device__ __nv_bfloat16 g_woh[1024*1024], g_wol[1024*1024];   // transposed N x K

__device__ __forceinline__ void bf16split(float x, __nv_bfloat16& hi, __nv_bfloat16& lo) {
    hi = __float2bfloat16_rn(x);
    lo = __float2bfloat16_rn(x - __bfloat162float(hi));
}

// ---------------------------------------------------------------------------
// Pre-pass 1: elementwise split (row-major preserved)
// ---------------------------------------------------------------------------
__global__ void split_plain_kernel(const float* __restrict__ in,
                                   __nv_bfloat16* __restrict__ hi,
                                   __nv_bfloat16* __restrict__ lo)
{
    int i = (blockIdx.x * 256 + threadIdx.x) * 4;
    float4 v = *reinterpret_cast<const float4*>(in + i);
    __nv_bfloat16 h0,l0,h1,l1,h2,l2,h3,l3;
    bf16split(v.x,h0,l0); bf16split(v.y,h1,l1);
    bf16split(v.z,h2,l2); bf16split(v.w,h3,l3);
    *reinterpret_cast<__nv_bfloat162*>(hi + i)     = __nv_bfloat162(h0,h1);
    *reinterpret_cast<__nv_bfloat162*>(hi + i + 2) = __nv_bfloat162(h2,h3);
    *reinterpret_cast<__nv_bfloat162*>(lo + i)     = __nv_bfloat162(l0,l1);
    *reinterpret_cast<__nv_bfloat162*>(lo + i + 2) = __nv_bfloat162(l2,l3);
}

// ---------------------------------------------------------------------------
// Pre-pass 2: split + transpose. in: R x C (fp32) -> hiT/loT: C x R (bf16)
// ---------------------------------------------------------------------------
__global__ void transpose_split_kernel(const float* __restrict__ in,
                                       __nv_bfloat16* __restrict__ hiT,
                                       __nv_bfloat16* __restrict__ loT,
                                       int R, int C)
{
    __shared__ float t[32][33];
    const int tx = threadIdx.x, ty = threadIdx.y;
    const int r0 = blockIdx.y * 32, c0 = blockIdx.x * 32;
    #pragma unroll
    for (int i = 0; i < 4; i++)
        t[ty + i*8][tx] = in[(long)(r0 + ty + i*8) * C + c0 + tx];
    __syncthreads();
    #pragma unroll
    for (int i = 0; i < 4; i++) {
        float v = t[tx][ty + i*8];
        __nv_bfloat16 h, l;
        bf16split(v, h, l);
        long o = (long)(c0 + ty + i*8) * R + r0 + tx;
        hiT[o] = h; loT[o] = l;
    }
}

// ---------------------------------------------------------------------------
// bf16 3-term GEMM: CTA tile 128x128, 4 warps (128 thr) in 2x2 of 64x64 warp
// tiles, BK=32 double-buffered, ldmatrix fragments. smem 80KB -> 2 CTAs/SM.
// ---------------------------------------------------------------------------
#define KP 40
#define GPLANE (128*KP)
#define GEMM_SMEM_BYTES (8 * GPLANE * (int)sizeof(__nv_bfloat16))

__device__ __forceinline__ void cpasync16(__nv_bfloat16* smem, const __nv_bfloat16* g) {
    uint32_t s = (uint32_t)__cvta_generic_to_shared(smem);
    asm volatile("cp.async.cg.shared.global [%0], [%1], 16;\n" :: "r"(s), "l"(g));
}

__device__ __forceinline__ void mma_bf16(float* c, const uint32_t* a, const uint32_t* b) {
    asm volatile(
        "mma.sync.aligned.m16n8k16.row.col.f32.bf16.bf16.f32 "
        "{%0,%1,%2,%3}, {%4,%5,%6,%7}, {%8,%9}, {%0,%1,%2,%3};"
        : "+f"(c[0]), "+f"(c[1]), "+f"(c[2]), "+f"(c[3])
        : "r"(a[0]), "r"(a[1]), "r"(a[2]), "r"(a[3]), "r"(b[0]), "r"(b[1]));
}

__device__ __forceinline__ void ldsm_x4(uint32_t* r, uint32_t addr) {
    asm volatile("ldmatrix.sync.aligned.m8n8.x4.shared.b16 {%0,%1,%2,%3}, [%4];"
                 : "=r"(r[0]), "=r"(r[1]), "=r"(r[2]), "=r"(r[3]) : "r"(addr));
}

template<int N, bool IS_QKV>
__global__ __launch_bounds__(128, 2)
void bf16_gemm_kernel(const __nv_bfloat16* __restrict__ Ahg,
                      const __nv_bfloat16* __restrict__ Alg,
                      const __nv_bfloat16* __restrict__ Bhg,
                      const __nv_bfloat16* __restrict__ Blg,
                      float* __restrict__ Out)
{
    extern __shared__ __nv_bfloat16 smg[];
    __nv_bfloat16* Ah = smg;
    __nv_bfloat16* Al = smg + 2*GPLANE;
    __nv_bfloat16* Bh = smg + 4*GPLANE;
    __nv_bfloat16* Bl = smg + 6*GPLANE;

    const int K = 1024;
    const int tid  = threadIdx.x;
    const int lane = tid & 31;
    const int wid  = tid >> 5;       // 0..3
    const int wm   = wid & 1;        // 2 m-slabs of 64
    const int wn   = wid >> 1;       // 2 n-slabs of 64
    const int m0 = blockIdx.y * 128;
    const int n0 = blockIdx.x * 128;

    // ldmatrix per-lane offset
    const int lrow = ((lane >> 3) & 1) * 8 + (lane & 7);
    const int lkq  = (lane >> 4) * 8;
    const uint32_t lmo = (uint32_t)((lrow * KP + lkq) * 2);

    const uint32_t sAh = (uint32_t)__cvta_generic_to_shared(Ah);
    const uint32_t sAl = sAh + 2*GPLANE*2;
    const uint32_t sBh = sAh + 4*GPLANE*2;
    const uint32_t sBl = sAh + 6*GPLANE*2;

    float acc[4][8][4];
    #pragma unroll
    for (int mt = 0; mt < 4; mt++)
        #pragma unroll
        for (int nt = 0; nt < 8; nt++)
            #pragma unroll
            for (int i = 0; i < 4; i++) acc[mt][nt][i] = 0.f;

    // loader: per plane 512 chunks of 16B, 128 threads -> 4 chunks/thread
    auto load_tiles = [&](int k0, int buf) {
        #pragma unroll
        for (int u = 0; u < 4; u++) {
            int c = tid + u*128;
            int row = c >> 2, kc = (c & 3) * 8;
            long go = (long)(m0 + row)*K + k0 + kc;
            cpasync16(&Ah[buf*GPLANE + row*KP + kc], Ahg + go);
            cpasync16(&Al[buf*GPLANE + row*KP + kc], Alg + go);
        }
        #pragma unroll
        for (int u = 0; u < 4; u++) {
            int c = tid + u*128;
            int row = c >> 2, kc = (c & 3) * 8;
            long go = (long)(n0 + row)*K + k0 + kc;
            cpasync16(&Bh[buf*GPLANE + row*KP + kc], Bhg + go);
            cpasync16(&Bl[buf*GPLANE + row*KP + kc], Blg + go);
        }
        asm volatile("cp.async.commit_group;\n");
    };

    load_tiles(0, 0);

    const int NIT = K / 32;
    for (int it = 0; it < NIT; ++it) {
        const int buf = it & 1;
        asm volatile("cp.async.wait_group 0;\n");
        __syncthreads();
        if (it + 1 < NIT) load_tiles((it+1)*32, buf ^ 1);

        const uint32_t bofs = (uint32_t)(buf*GPLANE*2);

        #pragma unroll
        for (int ks = 0; ks < 2; ks++) {
            const uint32_t kbo = bofs + (uint32_t)(ks*16*2) + lmo;

            uint32_t ahf[4][4], alf[4][4];
            #pragma unroll
            for (int mt = 0; mt < 4; mt++) {
                uint32_t ro = (uint32_t)((wm*64 + mt*16) * KP * 2);
                ldsm_x4(ahf[mt], sAh + ro + kbo);
                ldsm_x4(alf[mt], sAl + ro + kbo);
            }
            uint32_t bhf[8][2], blf[8][2];
            #pragma unroll
            for (int p = 0; p < 4; p++) {
                uint32_t ro = (uint32_t)((wn*64 + p*16) * KP * 2);
                uint32_t r[4];
                ldsm_x4(r, sBh + ro + kbo);
                bhf[2*p+0][0] = r[0]; bhf[2*p+1][0] = r[1];
                bhf[2*p+0][1] = r[2]; bhf[2*p+1][1] = r[3];
                ldsm_x4(r, sBl + ro + kbo);
                blf[2*p+0][0] = r[0]; blf[2*p+1][0] = r[1];
                blf[2*p+0][1] = r[2]; blf[2*p+1][1] = r[3];
            }
            #pragma unroll
            for (int mt = 0; mt < 4; mt++)
                #pragma unroll
                for (int nt = 0; nt < 8; nt++) {
                    mma_bf16(acc[mt][nt], ahf[mt], blf[nt]);  // hi*lo
                    mma_bf16(acc[mt][nt], alf[mt], bhf[nt]);  // lo*hi
                    mma_bf16(acc[mt][nt], ahf[mt], bhf[nt]);  // hi*hi
                }
        }
        __syncthreads();
    }

    #pragma unroll
    for (int mt = 0; mt < 4; mt++) {
        #pragma unroll
        for (int i = 0; i < 2; i++) {
            int row = m0 + wm*64 + mt*16 + (lane >> 2) + i*8;
            #pragma unroll
            for (int nt = 0; nt < 8; nt++) {
                int col = n0 + wn*64 + nt*8 + (lane & 3)*2;
                float2 v = make_float2(acc[mt][nt][i*2+0], acc[mt][nt][i*2+1]);
                if (IS_QKV) {
                    int b = row >> 11, s = row & 2047;
                    int which = col >> 10;
                    int h = (col >> 6) & 15;
                    int dh = col & 63;
                    float* dst = (which == 0) ? g_q : (which == 1) ? g_k : g_v;
                    *reinterpret_cast<float2*>(
                        &dst[(((long)(b*NHEAD + h))*S_LEN + s)*DHEAD + dh]) = v;
                } else {
                    *reinterpret_cast<float2*>(&Out[(long)row*N + col]) = v;
                }
            }
        }
    }
}

// ---------------------------------------------------------------------------
// Banded attention. Qs/Ks pitch 65, S overlays K, 2 CTAs/SM.
// Epilogue writes bf16 hi/lo planes directly (no fp32 round-trip).
// ---------------------------------------------------------------------------
#define QS_P 65
#define KS_P 65
#define ATTN_SMEM_FLOATS (64*QS_P + 192*KS_P + 192*64)

__global__ __launch_bounds__(256)
void attn_kernel(const float* __restrict__ bias)
{
    extern __shared__ float sm[];
    float* Qs = sm;
    float* Ks = sm + 64*QS_P;
    float* Vs = sm + 64*QS_P + 192*KS_P;
    float* Ss = Ks;

    const int tid = threadIdx.x;
    const int qt = blockIdx.x;
    const int bh = blockIdx.y;
    const int qstart = qt * 64;
    const int jbase = qstart - 128;

    const float* qg = g_q + (long)bh * S_LEN * DHEAD;
    const float* kg = g_k + (long)bh * S_LEN * DHEAD;
    const float* vg = g_v + (long)bh * S_LEN * DHEAD;

    for (int idx = tid; idx < 64*64; idx += 256)
        Qs[(idx >> 6)*QS_P + (idx & 63)] = qg[(long)(qstart + (idx >> 6))*DHEAD + (idx & 63)];
    for (int idx = tid; idx < 192*64; idx += 256) {
        int j = jbase + (idx >> 6);
        float kv = 0.f, vv = 0.f;
        if (j >= 0) {
            kv = kg[(long)j*DHEAD + (idx & 63)];
            vv = vg[(long)j*DHEAD + (idx & 63)];
        }
        Ks[(idx >> 6)*KS_P + (idx & 63)] = kv;
        Vs[idx] = vv;
    }
    __syncthreads();

    const int ty = tid >> 4, tx = tid & 15;

    {
        float acc[4][12];
        #pragma unroll
        for (int i = 0; i < 4; i++)
            #pragma unroll
            for (int j = 0; j < 12; j++) acc[i][j] = 0.f;

        #pragma unroll 4
        for (int k = 0; k < 64; k++) {
            float rq[4], rk[12];
            #pragma unroll
            for (int i = 0; i < 4; i++) rq[i] = Qs[(ty*4+i)*QS_P + k];
            #pragma unroll
            for (int j = 0; j < 12; j++) rk[j] = Ks[(tx*12+j)*KS_P + k];
            #pragma unroll
            for (int i = 0; i < 4; i++)
                #pragma unroll
                for (int j = 0; j < 12; j++)
                    acc[i][j] = fmaf(rq[i], rk[j], acc[i][j]);
        }
        __syncthreads();

        const float scale = 0.125f;
        const float* bb = bias + (long)bh * S_LEN * S_LEN;
        #pragma unroll
        for (int i = 0; i < 4; i++) {
            int gi = qstart + ty*4 + i;
            #pragma unroll
            for (int j = 0; j < 12; j++) {
                int c = tx*12 + j;
                int gj = jbase + c;
                float val = NEGBIG;
                if (gj >= 0 && gj <= gi && (gi - gj) <= 128)
                    val = acc[i][j]*scale + bb[(long)gi*S_LEN + gj];
                Ss[(ty*4+i)*192 + c] = val;
            }
        }
    }
    __syncthreads();

    {
        const int w = tid >> 5, lane = tid & 31;
        for (int rr = 0; rr < 8; rr++) {
            int r = w*8 + rr;
            float vals[6];
            float m = NEGBIG;
            #pragma unroll
            for (int t = 0; t < 6; t++) {
                vals[t] = Ss[r*192 + t*32 + lane];
                m = fmaxf(m, vals[t]);
            }
            #pragma unroll
            for (int o = 16; o > 0; o >>= 1)
                m = fmaxf(m, __shfl_xor_sync(0xffffffffu, m, o));
            float ssum = 0.f;
            #pragma unroll
            for (int t = 0; t < 6; t++) {
                vals[t] = __expf(vals[t] - m);
                ssum += vals[t];
            }
            #pragma unroll
            for (int o = 16; o > 0; o >>= 1)
                ssum += __shfl_xor_sync(0xffffffffu, ssum, o);
            float inv = 1.f / ssum;
            #pragma unroll
            for (int t = 0; t < 6; t++)
                Ss[r*192 + t*32 + lane] = vals[t] * inv;
        }
    }
    __syncthreads();

    {
        float acc[4][4];
        #pragma unroll
        for (int i = 0; i < 4; i++)
            #pragma unroll
            for (int j = 0; j < 4; j++) acc[i][j] = 0.f;

        #pragma unroll 4
        for (int k = 0; k < 192; k++) {
            float rp[4], rv[4];
            #pragma unroll
            for (int i = 0; i < 4; i++) rp[i] = Ss[(ty*4+i)*192 + k];
            #pragma unroll
            for (int j = 0; j < 4; j++) rv[j] = Vs[k*64 + tx*4 + j];
            #pragma unroll
            for (int i = 0; i < 4; i++)
                #pragma unroll
                for (int j = 0; j < 4; j++)
                    acc[i][j] = fmaf(rp[i], rv[j], acc[i][j]);
        }

        const int b = bh >> 4, h = bh & 15;
        #pragma unroll
        for (int i = 0; i < 4; i++) {
            int gi = qstart + ty*4 + i;
            long o = ((long)(b*S_LEN + gi))*D_MODEL + h*DHEAD + tx*4;
            __nv_bfloat16 h0,l0,h1,l1,h2,l2,h3,l3;
            bf16split(acc[i][0], h0, l0);
            bf16split(acc[i][1], h1, l1);
            bf16split(acc[i][2], h2, l2);
            bf16split(acc[i][3], h3, l3);
            *reinterpret_cast<__nv_bfloat162*>(&g_ath[o])   = __nv_bfloat162(h0, h1);
            *reinterpret_cast<__nv_bfloat162*>(&g_ath[o+2]) = __nv_bfloat162(h2, h3);
            *reinterpret_cast<__nv_bfloat162*>(&g_atl[o])   = __nv_bfloat162(l0, l1);
            *reinterpret_cast<__nv_bfloat162*>(&g_atl[o+2]) = __nv_bfloat162(l2, l3);
        }
    }
}

// ---------------------------------------------------------------------------
extern "C" void kernel_launch(void* const* d_in, const int* in_sizes, int n_in,
                              void* d_out, int out_size)
{
    const float* x    = (const float*)d_in[0];
    const float* bias = (const float*)d_in[1];
    // d_in[2] = causal mask (recomputed analytically in-kernel)
    const float* Wqkv = (const float*)d_in[3];
    const float* Wout = (const float*)d_in[4];
    float* out = (float*)d_out;

    __nv_bfloat16 *xh, *xl, *ath, *atl, *wqh, *wql, *woh, *wol;
    cudaGetSymbolAddress((void**)&xh,  g_xh);  cudaGetSymbolAddress((void**)&xl,  g_xl);
    cudaGetSymbolAddress((void**)&ath, g_ath); cudaGetSymbolAddress((void**)&atl, g_atl);
    cudaGetSymbolAddress((void**)&wqh, g_wqh); cudaGetSymbolAddress((void**)&wql, g_wql);
    cudaGetSymbolAddress((void**)&woh, g_woh); cudaGetSymbolAddress((void**)&wol, g_wol);

    cudaFuncSetAttribute(bf16_gemm_kernel<3072, true>,
                         cudaFuncAttributeMaxDynamicSharedMemorySize, GEMM_SMEM_BYTES);
    cudaFuncSetAttribute(bf16_gemm_kernel<1024, false>,
                         cudaFuncAttributeMaxDynamicSharedMemorySize, GEMM_SMEM_BYTES);
    cudaFuncSetAttribute(attn_kernel,
                         cudaFuncAttributeMaxDynamicSharedMemorySize,
                         ATTN_SMEM_FLOATS * (int)sizeof(float));

    // Pre-passes: split x; split+transpose weights
    split_plain_kernel<<<4096, 256>>>(x, xh, xl);
    transpose_split_kernel<<<dim3(3072/32, 1024/32), dim3(32, 8)>>>(Wqkv, wqh, wql, 1024, 3072);
    transpose_split_kernel<<<dim3(1024/32, 1024/32), dim3(32, 8)>>>(Wout, woh, wol, 1024, 1024);

    // QKV projection (M=4096, N=3072)
    bf16_gemm_kernel<3072, true><<<dim3(24, 32), 128, GEMM_SMEM_BYTES>>>(
        xh, xl, wqh, wql, nullptr);

    // Banded attention (writes bf16 planes directly)
    attn_kernel<<<dim3(32, 32), 256, ATTN_SMEM_FLOATS * (int)sizeof(float)>>>(bias);

    // Output projection (M=4096, N=1024)
    bf16_gemm_kernel<1024, false><<<dim3(8, 32), 128, GEMM_SMEM_BYTES>>>(
        ath, atl, woh, wol, out);
}